// round 1
// baseline (speedup 1.0000x reference)
#include <cuda_runtime.h>
#include <math.h>

#define BB 128
#define TT 1024
#define HH 512
#define GG 1536
#define NCTA 128

// ---------------- scratch (static device globals; no allocation) ----------------
__device__ float g_xp[(size_t)BB * TT * GG];   // input projections [B*T, 3H]
__device__ float g_h1[(size_t)BB * TT * HH];   // layer-0 hidden sequence [B*T, H]
__device__ float g_hbuf[2][BB * HH];           // double-buffered h state
__device__ unsigned g_count = 0;               // grid barrier arrival count
__device__ volatile unsigned g_gen = 0;        // grid barrier generation

// ---------------- SGEMM: C[M,N] = A[M,K] @ W[N,K]^T + bias[N] ----------------
// M = 131072, N = 1536. BM=BN=128, BK=16, 256 threads, 8x8 microtile.
template <int K>
__global__ void __launch_bounds__(256, 2) sgemm_bias(
    const float* __restrict__ A, const float* __restrict__ W,
    const float* __restrict__ bias, float* __restrict__ C)
{
    __shared__ float As[16][128];
    __shared__ float Bs[16][128];

    const int tid = threadIdx.x;
    const int tx = tid & 15;       // N direction
    const int ty = tid >> 4;       // M direction
    const int m0 = blockIdx.y * 128;
    const int n0 = blockIdx.x * 128;

    float acc[8][8];
#pragma unroll
    for (int i = 0; i < 8; i++)
#pragma unroll
        for (int j = 0; j < 8; j++) acc[i][j] = 0.f;

    for (int k0 = 0; k0 < K; k0 += 16) {
        __syncthreads();
#pragma unroll
        for (int l = 0; l < 2; l++) {
            int idx = tid + l * 256;      // 0..511 float4 slots
            int row = idx >> 2;           // 0..127
            int c4  = (idx & 3) * 4;      // 0,4,8,12
            float4 av = *(const float4*)&A[(size_t)(m0 + row) * K + k0 + c4];
            As[c4 + 0][row] = av.x; As[c4 + 1][row] = av.y;
            As[c4 + 2][row] = av.z; As[c4 + 3][row] = av.w;
            float4 wv = *(const float4*)&W[(size_t)(n0 + row) * K + k0 + c4];
            Bs[c4 + 0][row] = wv.x; Bs[c4 + 1][row] = wv.y;
            Bs[c4 + 2][row] = wv.z; Bs[c4 + 3][row] = wv.w;
        }
        __syncthreads();
#pragma unroll
        for (int k = 0; k < 16; k++) {
            float a[8], b[8];
            *(float4*)&a[0] = *(float4*)&As[k][ty * 4];
            *(float4*)&a[4] = *(float4*)&As[k][64 + ty * 4];
            *(float4*)&b[0] = *(float4*)&Bs[k][tx * 4];
            *(float4*)&b[4] = *(float4*)&Bs[k][64 + tx * 4];
#pragma unroll
            for (int i = 0; i < 8; i++)
#pragma unroll
                for (int j = 0; j < 8; j++) acc[i][j] += a[i] * b[j];
        }
    }

#pragma unroll
    for (int i = 0; i < 8; i++) {
        int m = m0 + (i >> 2) * 64 + ty * 4 + (i & 3);
#pragma unroll
        for (int jh = 0; jh < 2; jh++) {
            int n = n0 + jh * 64 + tx * 4;
            float4 bv = *(const float4*)&bias[n];
            float4 o;
            o.x = acc[i][jh * 4 + 0] + bv.x;
            o.y = acc[i][jh * 4 + 1] + bv.y;
            o.z = acc[i][jh * 4 + 2] + bv.z;
            o.w = acc[i][jh * 4 + 3] + bv.w;
            *(float4*)&C[(size_t)m * GG + n] = o;
        }
    }
}

// ---------------- software grid barrier (all 128 CTAs resident) ----------------
__device__ __forceinline__ void grid_barrier(unsigned& gen)
{
    __threadfence();          // make this thread's global writes visible
    __syncthreads();
    if (threadIdx.x == 0) {
        unsigned arrived = atomicAdd(&g_count, 1u);
        if (arrived == NCTA - 1) {
            g_count = 0;
            __threadfence();
            g_gen = gen + 1;  // release
        } else {
            while (g_gen == gen) { }  // spin on volatile
        }
    }
    __syncthreads();
    __threadfence();          // acquire side
    gen++;
}

// ---------------- persistent GRU layer ----------------
// 128 CTAs x 256 threads. CTA c owns h-columns [4c, 4c+4) => gate rows
// {col, 512+col, 1024+col}. Weights persist in SMEM. h double-buffered in
// g_hbuf; one grid barrier per timestep.
// Thread mapping: bg = tid&31 (batch group), j = (tid>>5)&3 (h-col within CTA),
// kh = tid>>7 (K half: 0 -> k[0,256), 1 -> k[256,512)).
__global__ void __launch_bounds__(256, 1) gru_layer(
    const float* __restrict__ xp,    // [B*T, 1536] (includes b_ih)
    const float* __restrict__ Whh,   // [1536, 512]
    const float* __restrict__ bhh,   // [1536]
    float* __restrict__ seq_out)     // [B*T, 512] or nullptr
{
    extern __shared__ float sm[];
    float* ws  = sm;                        // [12][512] weight rows
    float* hs  = sm + 12 * 512;             // [2][128][68] h tile (kh, b, k)
    float* red = hs + 2 * 128 * 68;         // [128][12] cross-half reduction

    const int tid = threadIdx.x;
    const int c   = blockIdx.x;
    const int bg  = tid & 31;
    const int j   = (tid >> 5) & 3;
    const int kh  = tid >> 7;
    const int col = c * 4 + j;

    // load W_hh rows for this CTA's 12 gate rows: ws[(g*4+jj)*512 + k]
    for (int idx = tid; idx < 12 * 512; idx += 256) {
        int r  = idx >> 9;          // 0..11
        int k  = idx & 511;
        int g  = r >> 2, jj = r & 3;
        ws[idx] = Whh[(size_t)(g * 512 + c * 4 + jj) * 512 + k];
    }
    // zero initial h for owned columns
    for (int idx = tid; idx < 512; idx += 256) {
        int b = idx >> 2, jj = idx & 3;
        g_hbuf[0][b * 512 + c * 4 + jj] = 0.f;
    }

    unsigned gen = g_gen;        // stable: no CTA advances gen until all arrive
    grid_barrier(gen);

    // cooperative loader mapping (coalesced 256B row segments)
    const int lane = tid & 31;
    const int grp  = tid >> 5;           // 0..7
    const int l_k4 = (lane & 15) * 4;    // 0..60
    const int l_kh = lane >> 4;          // 0/1

    const float* wR = &ws[(0 * 4 + j) * 512];
    const float* wZ = &ws[(1 * 4 + j) * 512];
    const float* wN = &ws[(2 * 4 + j) * 512];

    for (int t = 0; t < TT; t++) {
        const float* hcur = g_hbuf[t & 1];
        float*       hnxt = g_hbuf[(t & 1) ^ 1];

        float aR[4] = {0.f, 0.f, 0.f, 0.f};
        float aZ[4] = {0.f, 0.f, 0.f, 0.f};
        float aN[4] = {0.f, 0.f, 0.f, 0.f};

        for (int cc = 0; cc < 4; cc++) {
            // stage h[:, kh*256 + cc*64 .. +64) for both kh halves into SMEM
#pragma unroll
            for (int it = 0; it < 16; it++) {
                int b = grp + 8 * it;
                float4 v = *(const float4*)&hcur[b * 512 + l_kh * 256 + cc * 64 + l_k4];
                *(float4*)&hs[(l_kh * 128 + b) * 68 + l_k4] = v;
            }
            __syncthreads();

            const float* wRk = wR + kh * 256 + cc * 64;
            const float* wZk = wZ + kh * 256 + cc * 64;
            const float* wNk = wN + kh * 256 + cc * 64;
#pragma unroll 4
            for (int kk = 0; kk < 16; kk++) {
                float4 wr = *(const float4*)&wRk[kk * 4];
                float4 wz = *(const float4*)&wZk[kk * 4];
                float4 wn = *(const float4*)&wNk[kk * 4];
#pragma unroll
                for (int i = 0; i < 4; i++) {
                    int b = bg + 32 * i;
                    float4 hv = *(const float4*)&hs[(kh * 128 + b) * 68 + kk * 4];
                    aR[i] += hv.x * wr.x + hv.y * wr.y + hv.z * wr.z + hv.w * wr.w;
                    aZ[i] += hv.x * wz.x + hv.y * wz.y + hv.z * wz.z + hv.w * wz.w;
                    aN[i] += hv.x * wn.x + hv.y * wn.y + hv.z * wn.z + hv.w * wn.w;
                }
            }
            __syncthreads();
        }

        // cross-half reduction: kh==1 dumps partials, kh==0 finishes + gates
        if (kh == 1) {
            float* rp = &red[(tid - 128) * 12];
#pragma unroll
            for (int i = 0; i < 4; i++) {
                rp[i] = aR[i]; rp[4 + i] = aZ[i]; rp[8 + i] = aN[i];
            }
        }
        __syncthreads();
        if (kh == 0) {
            const float* rp = &red[tid * 12];
            float bR = bhh[col], bZ = bhh[512 + col], bN = bhh[1024 + col];
#pragma unroll
            for (int i = 0; i < 4; i++) {
                int b = bg + 32 * i;
                float ghr = aR[i] + rp[i]     + bR;
                float ghz = aZ[i] + rp[4 + i] + bZ;
                float ghn = aN[i] + rp[8 + i] + bN;
                size_t xbase = ((size_t)b * TT + t) * GG;
                float xr = xp[xbase + col];
                float xz = xp[xbase + 512 + col];
                float xn = xp[xbase + 1024 + col];
                float r = 1.f / (1.f + __expf(-(xr + ghr)));
                float z = 1.f / (1.f + __expf(-(xz + ghz)));
                float n = tanhf(xn + r * ghn);
                float ho = hcur[b * 512 + col];
                float hv = (1.f - z) * n + z * ho;
                hnxt[b * 512 + col] = hv;
                if (seq_out) seq_out[((size_t)b * TT + t) * HH + col] = hv;
            }
        }
        grid_barrier(gen);
    }
}

// ---------------- final linear: out[b] = h_final[b,:] . W_lin + b_lin ----------------
__global__ void final_linear(const float* __restrict__ Wl,
                             const float* __restrict__ bl,
                             float* __restrict__ out)
{
    __shared__ float ssum[4];
    int b = blockIdx.x, tid = threadIdx.x;
    const float* h = &g_hbuf[0][0] + b * 512;   // final state lands in buffer 0
    float s = 0.f;
    for (int k = tid; k < 512; k += 128) s += h[k] * Wl[k];
#pragma unroll
    for (int o = 16; o > 0; o >>= 1) s += __shfl_down_sync(0xffffffffu, s, o);
    if ((tid & 31) == 0) ssum[tid >> 5] = s;
    __syncthreads();
    if (tid == 0) out[b] = ssum[0] + ssum[1] + ssum[2] + ssum[3] + bl[0];
}

// ---------------- launch ----------------
extern "C" void kernel_launch(void* const* d_in, const int* in_sizes, int n_in,
                              void* d_out, int out_size)
{
    const float* x    = (const float*)d_in[0];
    const float* Wih0 = (const float*)d_in[1];
    const float* Whh0 = (const float*)d_in[2];
    const float* bih0 = (const float*)d_in[3];
    const float* bhh0 = (const float*)d_in[4];
    const float* Wih1 = (const float*)d_in[5];
    const float* Whh1 = (const float*)d_in[6];
    const float* bih1 = (const float*)d_in[7];
    const float* bhh1 = (const float*)d_in[8];
    const float* Wlin = (const float*)d_in[9];
    const float* blin = (const float*)d_in[10];
    float* out = (float*)d_out;

    float* xp = nullptr;
    float* h1 = nullptr;
    cudaGetSymbolAddress((void**)&xp, g_xp);
    cudaGetSymbolAddress((void**)&h1, g_h1);

    const int gru_smem = (12 * 512 + 2 * 128 * 68 + 128 * 12) * (int)sizeof(float);
    cudaFuncSetAttribute(gru_layer, cudaFuncAttributeMaxDynamicSharedMemorySize, gru_smem);

    dim3 gg(GG / 128, (BB * TT) / 128);   // (12, 1024)

    // layer 0
    sgemm_bias<256><<<gg, 256>>>(x, Wih0, bih0, xp);
    gru_layer<<<NCTA, 256, gru_smem>>>(xp, Whh0, bhh0, h1);
    // layer 1
    sgemm_bias<512><<<gg, 256>>>(h1, Wih1, bih1, xp);
    gru_layer<<<NCTA, 256, gru_smem>>>(xp, Whh1, bhh1, nullptr);
    // head
    final_linear<<<BB, 128>>>(Wlin, blin, out);
}

// round 4
// speedup vs baseline: 2.7946x; 2.7946x over previous
#include <cuda_runtime.h>
#include <cuda_bf16.h>
#include <math.h>
#include <stdint.h>

#define BB 128
#define TT 1024
#define HH 512
#define GG 1536
#define NCTA 128

// ---------------- device scratch (no allocation) ----------------
__device__ float g_xp[(size_t)BB * TT * GG];
__device__ __nv_bfloat16 g_xhi[(size_t)BB * TT * 256];
__device__ __nv_bfloat16 g_xlo[(size_t)BB * TT * 256];
__device__ __nv_bfloat16 g_h1hi[(size_t)BB * TT * HH];
__device__ __nv_bfloat16 g_h1lo[(size_t)BB * TT * HH];
__device__ __nv_bfloat16 g_w0hi[GG * 256], g_w0lo[GG * 256];
__device__ __nv_bfloat16 g_w1hi[GG * HH],  g_w1lo[GG * HH];
__device__ __nv_bfloat16 g_whhhi[2][16 * 96 * 512];
__device__ __nv_bfloat16 g_whhlo[2][16 * 96 * 512];
__device__ float g_h[2][BB * HH];
__device__ __nv_bfloat16 g_hbhi[2][BB * HH];
__device__ __nv_bfloat16 g_hblo[2][BB * HH];
__device__ unsigned g_count = 0;
__device__ volatile unsigned g_gen = 0;

// ---------------- PTX helpers (baseline PTX only: sm_80-era) ----------------
__device__ __forceinline__ uint32_t smem_u32(const void* p) {
    uint32_t a;
    asm("{ .reg .u64 t; cvta.to.shared.u64 t, %1; cvt.u32.u64 %0, t; }" : "=r"(a) : "l"(p));
    return a;
}

#define CP16(dst, src) \
    asm volatile("cp.async.cg.shared.global [%0], [%1], 16;" :: "r"(dst), "l"(src))
#define CPCOMMIT() asm volatile("cp.async.commit_group;")
#define CPWAIT0()  asm volatile("cp.async.wait_group 0;")
#define CPWAIT1()  asm volatile("cp.async.wait_group 1;")

#define LDSM4(r, a) \
    asm volatile("ldmatrix.sync.aligned.m8n8.x4.shared.b16 {%0,%1,%2,%3}, [%4];" \
        : "=r"((r)[0]), "=r"((r)[1]), "=r"((r)[2]), "=r"((r)[3]) : "r"(a))
#define LDSM2(r, a) \
    asm volatile("ldmatrix.sync.aligned.m8n8.x2.shared.b16 {%0,%1}, [%2];" \
        : "=r"((r)[0]), "=r"((r)[1]) : "r"(a))

#define MMA16816(c, a, b) \
    asm volatile("mma.sync.aligned.m16n8k16.row.col.f32.bf16.bf16.f32 " \
        "{%0,%1,%2,%3}, {%4,%5,%6,%7}, {%8,%9}, {%0,%1,%2,%3};" \
        : "+f"((c)[0]), "+f"((c)[1]), "+f"((c)[2]), "+f"((c)[3]) \
        : "r"((a)[0]), "r"((a)[1]), "r"((a)[2]), "r"((a)[3]), "r"((b)[0]), "r"((b)[1]))

// ---------------- grid barrier ----------------
__device__ __forceinline__ void grid_barrier(unsigned& gen) {
    __threadfence();
    __syncthreads();
    if (threadIdx.x == 0) {
        unsigned arrived = atomicAdd(&g_count, 1u);
        if (arrived == NCTA - 1) {
            g_count = 0;
            __threadfence();
            g_gen = gen + 1;
        } else {
            while (g_gen == gen) { }
        }
    }
    __syncthreads();
    __threadfence();
    gen++;
}

// ---------------- conversions ----------------
__global__ void split_f32(const float* __restrict__ src, size_t n,
                          __nv_bfloat16* __restrict__ hi, __nv_bfloat16* __restrict__ lo) {
    size_t i = (size_t)blockIdx.x * blockDim.x + threadIdx.x;
    if (i < n) {
        float v = src[i];
        __nv_bfloat16 h = __float2bfloat16(v);
        hi[i] = h;
        lo[i] = __float2bfloat16(v - __bfloat162float(h));
    }
}

// reorder Whh [1536,512] -> [16 ng][96][512]; slice row j = g*32 + jj
__global__ void split_whh(const float* __restrict__ W,
                          __nv_bfloat16* __restrict__ hi, __nv_bfloat16* __restrict__ lo) {
    int i = blockIdx.x * 256 + threadIdx.x;    // grid 3072
    int k = i & 511;
    int ro = i >> 9;
    int ng = ro / 96, j = ro % 96;
    int g = j >> 5, jj = j & 31;
    float v = W[(size_t)(g * 512 + ng * 32 + jj) * 512 + k];
    __nv_bfloat16 h = __float2bfloat16(v);
    hi[i] = h;
    lo[i] = __float2bfloat16(v - __bfloat162float(h));
}

// ---------------- mma.sync GEMM: C[M,1536] = A[M,K] @ W[1536,K]^T + bias ----------------
// BM=128, BN=128, BK=64, 256 threads (8 warps: wm=w>>2 in {0,1} x 64 rows, wn=w&3 x 32 cols).
// 3 accumulation passes: Ahi*Bhi, Alo*Bhi, Ahi*Blo. cp.async double-buffered.
template <int K>
__global__ void __launch_bounds__(256) gemm_mma(
    const __nv_bfloat16* __restrict__ Ahi, const __nv_bfloat16* __restrict__ Alo,
    const __nv_bfloat16* __restrict__ Bhi, const __nv_bfloat16* __restrict__ Blo,
    const float* __restrict__ bias, float* __restrict__ C)
{
    extern __shared__ char smx[];
    const uint32_t sb = smem_u32(smx);
    const int tid = threadIdx.x, w = tid >> 5, lane = tid & 31;
    const int wm = w >> 2, wn = w & 3;
    const int m0 = blockIdx.y * 128, n0 = blockIdx.x * 128;

    float c[4][4][4];
#pragma unroll
    for (int i = 0; i < 4; i++)
#pragma unroll
        for (int j = 0; j < 4; j++)
#pragma unroll
            for (int q = 0; q < 4; q++) c[i][j][q] = 0.f;

    const int a_r  = (lane & 7) + ((lane >> 3) & 1) * 8;   // 0..15
    const int a_co = lane >> 4;                            // 0/1
    const int b_r  = lane & 7;
    const int b_co = (lane >> 3) & 1;

    const int KC = K / 64;
    const int NIT = 3 * KC;

    // stage iteration 'it' into buffer 'buf'
    auto stage = [&](int it, int buf) {
        int p = it / KC;
        int kc = (it - p * KC) * 64;
        const __nv_bfloat16* Ap = (p == 1) ? Alo : Ahi;
        const __nv_bfloat16* Bp = (p == 2) ? Blo : Bhi;
#pragma unroll
        for (int j = 0; j < 4; j++) {
            int idx = tid + j * 256;           // 0..1023
            int r = idx >> 3, cc = idx & 7;
            uint32_t off = (uint32_t)(r * 128 + ((cc ^ (r & 7)) << 4));
            CP16(sb + buf * 32768 + off, Ap + (size_t)(m0 + r) * K + kc + cc * 8);
            CP16(sb + buf * 32768 + 16384 + off, Bp + (size_t)(n0 + r) * K + kc + cc * 8);
        }
        CPCOMMIT();
    };

    stage(0, 0);
    for (int it = 0; it < NIT; it++) {
        int buf = it & 1;
        if (it + 1 < NIT) { stage(it + 1, buf ^ 1); CPWAIT1(); } else { CPWAIT0(); }
        __syncthreads();

        const uint32_t Ab = sb + buf * 32768 + (wm * 64) * 128;
        const uint32_t Bb = sb + buf * 32768 + 16384 + (wn * 32) * 128;
#pragma unroll
        for (int kk = 0; kk < 4; kk++) {
            uint32_t a[4][4];
            uint32_t asw = (uint32_t)(((2 * kk + a_co) ^ (a_r & 7)) << 4);
#pragma unroll
            for (int mt = 0; mt < 4; mt++)
                LDSM4(a[mt], Ab + (mt * 16 + a_r) * 128 + asw);
            uint32_t bsw = (uint32_t)(((2 * kk + b_co) ^ (b_r & 7)) << 4);
#pragma unroll
            for (int nt = 0; nt < 4; nt++) {
                uint32_t b[2];
                LDSM2(b, Bb + (nt * 8 + b_r) * 128 + bsw);
#pragma unroll
                for (int mt = 0; mt < 4; mt++)
                    MMA16816(c[mt][nt], a[mt], b);
            }
        }
        __syncthreads();
    }

    // epilogue: bias + store
#pragma unroll
    for (int nt = 0; nt < 4; nt++) {
        int col = n0 + wn * 32 + nt * 8 + (lane & 3) * 2;
        float2 bv = *(const float2*)&bias[col];
#pragma unroll
        for (int mt = 0; mt < 4; mt++) {
            int row = m0 + wm * 64 + mt * 16 + (lane >> 2);
            float2 v0 = { c[mt][nt][0] + bv.x, c[mt][nt][1] + bv.y };
            float2 v1 = { c[mt][nt][2] + bv.x, c[mt][nt][3] + bv.y };
            *(float2*)&C[(size_t)row * GG + col] = v0;
            *(float2*)&C[(size_t)(row + 8) * GG + col] = v1;
        }
    }
}

// ---------------- persistent mma.sync GRU layer ----------------
// 128 CTAs: ng = blockIdx.x & 15 (32 h-cols -> 96 gate rows), mg = blockIdx.x >> 4 (16 batches).
// W slice (96x512 hi+lo) persistent in swizzled SMEM. Per step: stage h tile (16x512 hi+lo),
// D[16,96] via mma bf16x3 with 2-way K split across warps, SMEM reduce, fused gate epilogue.
__global__ void __launch_bounds__(256, 1) gru_mma(
    const float* __restrict__ xp,
    const __nv_bfloat16* __restrict__ Whi_g, const __nv_bfloat16* __restrict__ Wlo_g,
    const float* __restrict__ bhh,
    __nv_bfloat16* __restrict__ seqhi, __nv_bfloat16* __restrict__ seqlo)
{
    extern __shared__ char smx[];
    const uint32_t sb = smem_u32(smx);
    float* sbias = (float*)smx;                    // 96 floats
    const uint32_t W_HI = 512;
    const uint32_t W_LO = 512 + 98304;
    const uint32_t A_HI = 512 + 196608;
    const uint32_t A_LO = A_HI + 16384;
    float* dred = (float*)(smx + A_HI);            // overlay: [2][16][stride 100]

    const int tid = threadIdx.x, w = tid >> 5, lane = tid & 31;
    const int nq = w & 3, kh = w >> 2;
    const int ng = blockIdx.x & 15, mg = blockIdx.x >> 4;

    // persistent W slice, swizzled (row = 1024B, chunk' = chunk ^ (row&7))
    const __nv_bfloat16* wh = Whi_g + (size_t)ng * 96 * 512;
    const __nv_bfloat16* wl = Wlo_g + (size_t)ng * 96 * 512;
    for (int idx = tid; idx < 6144; idx += 256) {
        int r = idx >> 6, cc = idx & 63;
        uint32_t off = (uint32_t)(r * 1024 + ((cc ^ (r & 7)) << 4));
        *(uint4*)(smx + W_HI + off) = *(const uint4*)(wh + r * 512 + cc * 8);
        *(uint4*)(smx + W_LO + off) = *(const uint4*)(wl + r * 512 + cc * 8);
    }
    if (tid < 96) sbias[tid] = bhh[(tid >> 5) * 512 + ng * 32 + (tid & 31)];

    // zero owned region of initial state
    if (tid < 128) {
        int b = mg * 16 + (tid >> 3);
        int cc = ng * 32 + (tid & 7) * 4;
        float4 z4 = {0.f, 0.f, 0.f, 0.f};
        uint2 zb = {0u, 0u};
        *(float4*)&g_h[0][b * 512 + cc] = z4;
        *(uint2*)&g_hbhi[0][b * 512 + cc] = zb;
        *(uint2*)&g_hblo[0][b * 512 + cc] = zb;
    }

    unsigned gen = g_gen;
    grid_barrier(gen);

    const int a_r  = (lane & 7) + ((lane >> 3) & 1) * 8;
    const int a_co = lane >> 4;
    const int b_r  = lane & 7;
    const int b_co = (lane >> 3) & 1;
    const uint32_t AbHi = sb + A_HI + a_r * 1024;
    const uint32_t AbLo = sb + A_LO + a_r * 1024;
    uint32_t BbHi[3], BbLo[3];
#pragma unroll
    for (int f = 0; f < 3; f++) {
        int n = nq * 24 + f * 8 + b_r;
        BbHi[f] = sb + W_HI + n * 1024;
        BbLo[f] = sb + W_LO + n * 1024;
    }

    for (int t = 0; t < TT; t++) {
        const int cur = t & 1, nxt = cur ^ 1;

        // stage h tile (16 rows x 512, hi+lo) with cp.async
        const __nv_bfloat16* hh = &g_hbhi[cur][(size_t)mg * 16 * 512];
        const __nv_bfloat16* hl = &g_hblo[cur][(size_t)mg * 16 * 512];
#pragma unroll
        for (int j = 0; j < 4; j++) {
            int idx = tid + j * 256;           // 0..1023
            int r = idx >> 6, cc = idx & 63;
            uint32_t off = (uint32_t)(r * 1024 + ((cc ^ (r & 7)) << 4));
            CP16(sb + A_HI + off, hh + r * 512 + cc * 8);
            CP16(sb + A_LO + off, hl + r * 512 + cc * 8);
        }
        CPCOMMIT(); CPWAIT0();
        __syncthreads();

        float acc[3][4];
#pragma unroll
        for (int f = 0; f < 3; f++)
#pragma unroll
            for (int q = 0; q < 4; q++) acc[f][q] = 0.f;

#pragma unroll
        for (int kk0 = 0; kk0 < 16; kk0++) {
            int kk = kh * 16 + kk0;
            uint32_t ahi[4], alo[4];
            uint32_t asw = (uint32_t)(((2 * kk + a_co) ^ (a_r & 7)) << 4);
            LDSM4(ahi, AbHi + asw);
            LDSM4(alo, AbLo + asw);
            uint32_t bsw = (uint32_t)(((2 * kk + b_co) ^ (b_r & 7)) << 4);
#pragma unroll
            for (int f = 0; f < 3; f++) {
                uint32_t bh[2], bl[2];
                LDSM2(bh, BbHi[f] + bsw);
                LDSM2(bl, BbLo[f] + bsw);
                MMA16816(acc[f], ahi, bh);
                MMA16816(acc[f], alo, bh);
                MMA16816(acc[f], ahi, bl);
            }
        }
        __syncthreads();   // all LDSM done before dred overlays the A region

        // store K-half partials to smem
#pragma unroll
        for (int f = 0; f < 3; f++) {
            int colc = nq * 24 + f * 8 + (lane & 3) * 2;
            int b0 = lane >> 2;
            float* p0 = &dred[(kh * 16 + b0) * 100 + colc];
            float* p1 = &dred[(kh * 16 + b0 + 8) * 100 + colc];
            p0[0] = acc[f][0]; p0[1] = acc[f][1];
            p1[0] = acc[f][2]; p1[1] = acc[f][3];
        }
        __syncthreads();

        // fused gate epilogue: 512 (b, col) pairs over 256 threads
#pragma unroll
        for (int pp = 0; pp < 2; pp++) {
            int q = tid + pp * 256;
            int b = q >> 5, cc = q & 31;
            float Dr = dred[b * 100 + cc]      + dred[(16 + b) * 100 + cc];
            float Dz = dred[b * 100 + 32 + cc] + dred[(16 + b) * 100 + 32 + cc];
            float Dn = dred[b * 100 + 64 + cc] + dred[(16 + b) * 100 + 64 + cc];
            int bg = mg * 16 + b;
            int hc = ng * 32 + cc;
            size_t xb = ((size_t)bg * TT + t) * GG + hc;
            float xr = xp[xb], xz = xp[xb + 512], xn = xp[xb + 1024];
            float hold = g_h[cur][bg * 512 + hc];
            float r = __fdividef(1.f, 1.f + __expf(-(xr + Dr + sbias[cc])));
            float z = __fdividef(1.f, 1.f + __expf(-(xz + Dz + sbias[32 + cc])));
            float pre = xn + r * (Dn + sbias[64 + cc]);
            float e2 = __expf(2.f * pre);
            float n = 1.f - __fdividef(2.f, e2 + 1.f);
            float hv = (1.f - z) * n + z * hold;
            g_h[nxt][bg * 512 + hc] = hv;
            __nv_bfloat16 hb = __float2bfloat16(hv);
            float lo = hv - __bfloat162float(hb);
            g_hbhi[nxt][bg * 512 + hc] = hb;
            g_hblo[nxt][bg * 512 + hc] = __float2bfloat16(lo);
            if (seqhi) {
                size_t so = ((size_t)bg * TT + t) * HH + hc;
                seqhi[so] = hb;
                seqlo[so] = __float2bfloat16(lo);
            }
        }
        grid_barrier(gen);
    }
}

// ---------------- final linear ----------------
__global__ void final_linear(const float* __restrict__ Wl, const float* __restrict__ bl,
                             float* __restrict__ out)
{
    __shared__ float ssum[4];
    int b = blockIdx.x, tid = threadIdx.x;
    const float* h = &g_h[0][0] + b * 512;     // t=1023 writes buffer 0
    float s = 0.f;
    for (int k = tid; k < 512; k += 128) s += h[k] * Wl[k];
#pragma unroll
    for (int o = 16; o > 0; o >>= 1) s += __shfl_down_sync(0xffffffffu, s, o);
    if ((tid & 31) == 0) ssum[tid >> 5] = s;
    __syncthreads();
    if (tid == 0) out[b] = ssum[0] + ssum[1] + ssum[2] + ssum[3] + bl[0];
}

// ---------------- launch ----------------
extern "C" void kernel_launch(void* const* d_in, const int* in_sizes, int n_in,
                              void* d_out, int out_size)
{
    const float* x    = (const float*)d_in[0];
    const float* Wih0 = (const float*)d_in[1];
    const float* Whh0 = (const float*)d_in[2];
    const float* bih0 = (const float*)d_in[3];
    const float* bhh0 = (const float*)d_in[4];
    const float* Wih1 = (const float*)d_in[5];
    const float* Whh1 = (const float*)d_in[6];
    const float* bih1 = (const float*)d_in[7];
    const float* bhh1 = (const float*)d_in[8];
    const float* Wlin = (const float*)d_in[9];
    const float* blin = (const float*)d_in[10];
    float* out = (float*)d_out;

    float* xp;
    __nv_bfloat16 *xhi, *xlo, *h1hi, *h1lo, *w0hi, *w0lo, *w1hi, *w1lo, *whhhi, *whhlo;
    cudaGetSymbolAddress((void**)&xp, g_xp);
    cudaGetSymbolAddress((void**)&xhi, g_xhi);
    cudaGetSymbolAddress((void**)&xlo, g_xlo);
    cudaGetSymbolAddress((void**)&h1hi, g_h1hi);
    cudaGetSymbolAddress((void**)&h1lo, g_h1lo);
    cudaGetSymbolAddress((void**)&w0hi, g_w0hi);
    cudaGetSymbolAddress((void**)&w0lo, g_w0lo);
    cudaGetSymbolAddress((void**)&w1hi, g_w1hi);
    cudaGetSymbolAddress((void**)&w1lo, g_w1lo);
    cudaGetSymbolAddress((void**)&whhhi, g_whhhi);
    cudaGetSymbolAddress((void**)&whhlo, g_whhlo);
    const size_t WHH_SZ = 16 * 96 * 512;

    const int GEMM_SMEM = 2 * 32768;                        // 64 KB
    const int GRU_SMEM  = 512 + 2 * 98304 + 2 * 16384;      // 229888 B
    cudaFuncSetAttribute(gemm_mma<256>, cudaFuncAttributeMaxDynamicSharedMemorySize, GEMM_SMEM);
    cudaFuncSetAttribute(gemm_mma<512>, cudaFuncAttributeMaxDynamicSharedMemorySize, GEMM_SMEM);
    cudaFuncSetAttribute(gru_mma, cudaFuncAttributeMaxDynamicSharedMemorySize, GRU_SMEM);

    // conversions
    {
        size_t n = (size_t)BB * TT * 256;
        split_f32<<<(unsigned)((n + 255) / 256), 256>>>(x, n, xhi, xlo);
    }
    split_f32<<<(GG * 256 + 255) / 256, 256>>>(Wih0, (size_t)GG * 256, w0hi, w0lo);
    split_f32<<<(GG * 512 + 255) / 256, 256>>>(Wih1, (size_t)GG * 512, w1hi, w1lo);
    split_whh<<<3072, 256>>>(Whh0, whhhi, whhlo);
    split_whh<<<3072, 256>>>(Whh1, whhhi + WHH_SZ, whhlo + WHH_SZ);

    dim3 gg(GG / 128, (BB * TT) / 128);   // (12, 1024)

    // layer 0
    gemm_mma<256><<<gg, 256, GEMM_SMEM>>>(xhi, xlo, w0hi, w0lo, bih0, xp);
    gru_mma<<<NCTA, 256, GRU_SMEM>>>(xp, whhhi, whhlo, bhh0, h1hi, h1lo);
    // layer 1
    gemm_mma<512><<<gg, 256, GEMM_SMEM>>>(h1hi, h1lo, w1hi, w1lo, bih1, xp);
    gru_mma<<<NCTA, 256, GRU_SMEM>>>(xp, whhhi + WHH_SZ, whhlo + WHH_SZ, bhh1, nullptr, nullptr);
    // head
    final_linear<<<BB, 128>>>(Wlin, blin, out);
}

// round 5
// speedup vs baseline: 3.5451x; 1.2686x over previous
#include <cuda_runtime.h>
#include <cuda_bf16.h>
#include <math.h>
#include <stdint.h>

#define BB 128
#define TT 1024
#define HH 512
#define GG 1536
#define NCTA 128

// ---------------- device scratch (no allocation) ----------------
__device__ float g_xp[(size_t)BB * TT * GG];
__device__ __nv_bfloat16 g_xhi[(size_t)BB * TT * 256];
__device__ __nv_bfloat16 g_xlo[(size_t)BB * TT * 256];
__device__ __nv_bfloat16 g_h1hi[(size_t)BB * TT * HH];
__device__ __nv_bfloat16 g_h1lo[(size_t)BB * TT * HH];
__device__ __nv_bfloat16 g_w0hi[GG * 256], g_w0lo[GG * 256];
__device__ __nv_bfloat16 g_w1hi[GG * HH],  g_w1lo[GG * HH];
__device__ __nv_bfloat16 g_whhhi[2][16 * 96 * 512];
__device__ __nv_bfloat16 g_whhlo[2][16 * 96 * 512];
__device__ float g_h[2][BB * HH];
__device__ __nv_bfloat16 g_hbhi[2][BB * HH];
__device__ __nv_bfloat16 g_hblo[2][BB * HH];
// per-mg-group barrier state (stride 32 uints = 128B -> separate L2 lines)
__device__ unsigned g_cnt[8 * 32];
__device__ volatile unsigned g_genv[8 * 32];

// ---------------- PTX helpers (baseline PTX only: sm_80-era) ----------------
__device__ __forceinline__ uint32_t smem_u32(const void* p) {
    uint32_t a;
    asm("{ .reg .u64 t; cvta.to.shared.u64 t, %1; cvt.u32.u64 %0, t; }" : "=r"(a) : "l"(p));
    return a;
}

#define CP16(dst, src) \
    asm volatile("cp.async.cg.shared.global [%0], [%1], 16;" :: "r"(dst), "l"(src))
#define CPCOMMIT() asm volatile("cp.async.commit_group;")
#define CPWAIT0()  asm volatile("cp.async.wait_group 0;")
#define CPWAIT1()  asm volatile("cp.async.wait_group 1;")

#define LDSM4(r, a) \
    asm volatile("ldmatrix.sync.aligned.m8n8.x4.shared.b16 {%0,%1,%2,%3}, [%4];" \
        : "=r"((r)[0]), "=r"((r)[1]), "=r"((r)[2]), "=r"((r)[3]) : "r"(a))
#define LDSM2(r, a) \
    asm volatile("ldmatrix.sync.aligned.m8n8.x2.shared.b16 {%0,%1}, [%2];" \
        : "=r"((r)[0]), "=r"((r)[1]) : "r"(a))

#define MMA16816(c, a, b) \
    asm volatile("mma.sync.aligned.m16n8k16.row.col.f32.bf16.bf16.f32 " \
        "{%0,%1,%2,%3}, {%4,%5,%6,%7}, {%8,%9}, {%0,%1,%2,%3};" \
        : "+f"((c)[0]), "+f"((c)[1]), "+f"((c)[2]), "+f"((c)[3]) \
        : "r"((a)[0]), "r"((a)[1]), "r"((a)[2]), "r"((a)[3]), "r"((b)[0]), "r"((b)[1]))

// ---------------- group barrier: 16 CTAs sharing one mg group ----------------
__device__ __forceinline__ void group_barrier(int grp, unsigned& gen) {
    __threadfence();
    __syncthreads();
    if (threadIdx.x == 0) {
        unsigned a = atomicAdd(&g_cnt[grp * 32], 1u);
        if (a == 15) {
            g_cnt[grp * 32] = 0;
            __threadfence();
            g_genv[grp * 32] = gen + 1;   // release
        } else {
            while (g_genv[grp * 32] == gen) { }
        }
    }
    __syncthreads();
    __threadfence();
    gen++;
}

// ---------------- conversions ----------------
__global__ void split_f32(const float* __restrict__ src, size_t n,
                          __nv_bfloat16* __restrict__ hi, __nv_bfloat16* __restrict__ lo) {
    size_t i = (size_t)blockIdx.x * blockDim.x + threadIdx.x;
    if (i < n) {
        float v = src[i];
        __nv_bfloat16 h = __float2bfloat16(v);
        hi[i] = h;
        lo[i] = __float2bfloat16(v - __bfloat162float(h));
    }
}

// reorder Whh [1536,512] -> [16 ng][96][512]; slice row j = g*32 + jj
__global__ void split_whh(const float* __restrict__ W,
                          __nv_bfloat16* __restrict__ hi, __nv_bfloat16* __restrict__ lo) {
    int i = blockIdx.x * 256 + threadIdx.x;    // grid 3072
    int k = i & 511;
    int ro = i >> 9;
    int ng = ro / 96, j = ro % 96;
    int g = j >> 5, jj = j & 31;
    float v = W[(size_t)(g * 512 + ng * 32 + jj) * 512 + k];
    __nv_bfloat16 h = __float2bfloat16(v);
    hi[i] = h;
    lo[i] = __float2bfloat16(v - __bfloat162float(h));
}

// ---------------- mma.sync GEMM: C[M,1536] = A[M,K] @ W[1536,K]^T + bias ----------------
template <int K>
__global__ void __launch_bounds__(256) gemm_mma(
    const __nv_bfloat16* __restrict__ Ahi, const __nv_bfloat16* __restrict__ Alo,
    const __nv_bfloat16* __restrict__ Bhi, const __nv_bfloat16* __restrict__ Blo,
    const float* __restrict__ bias, float* __restrict__ C)
{
    extern __shared__ char smx[];
    const uint32_t sb = smem_u32(smx);
    const int tid = threadIdx.x, w = tid >> 5, lane = tid & 31;
    const int wm = w >> 2, wn = w & 3;
    const int m0 = blockIdx.y * 128, n0 = blockIdx.x * 128;

    float c[4][4][4];
#pragma unroll
    for (int i = 0; i < 4; i++)
#pragma unroll
        for (int j = 0; j < 4; j++)
#pragma unroll
            for (int q = 0; q < 4; q++) c[i][j][q] = 0.f;

    const int a_r  = (lane & 7) + ((lane >> 3) & 1) * 8;
    const int a_co = lane >> 4;
    const int b_r  = lane & 7;
    const int b_co = (lane >> 3) & 1;

    const int KC = K / 64;
    const int NIT = 3 * KC;

    auto stage = [&](int it, int buf) {
        int p = it / KC;
        int kc = (it - p * KC) * 64;
        const __nv_bfloat16* Ap = (p == 1) ? Alo : Ahi;
        const __nv_bfloat16* Bp = (p == 2) ? Blo : Bhi;
#pragma unroll
        for (int j = 0; j < 4; j++) {
            int idx = tid + j * 256;
            int r = idx >> 3, cc = idx & 7;
            uint32_t off = (uint32_t)(r * 128 + ((cc ^ (r & 7)) << 4));
            CP16(sb + buf * 32768 + off, Ap + (size_t)(m0 + r) * K + kc + cc * 8);
            CP16(sb + buf * 32768 + 16384 + off, Bp + (size_t)(n0 + r) * K + kc + cc * 8);
        }
        CPCOMMIT();
    };

    stage(0, 0);
    for (int it = 0; it < NIT; it++) {
        int buf = it & 1;
        if (it + 1 < NIT) { stage(it + 1, buf ^ 1); CPWAIT1(); } else { CPWAIT0(); }
        __syncthreads();

        const uint32_t Ab = sb + buf * 32768 + (wm * 64) * 128;
        const uint32_t Bb = sb + buf * 32768 + 16384 + (wn * 32) * 128;
#pragma unroll
        for (int kk = 0; kk < 4; kk++) {
            uint32_t a[4][4];
            uint32_t asw = (uint32_t)(((2 * kk + a_co) ^ (a_r & 7)) << 4);
#pragma unroll
            for (int mt = 0; mt < 4; mt++)
                LDSM4(a[mt], Ab + (mt * 16 + a_r) * 128 + asw);
            uint32_t bsw = (uint32_t)(((2 * kk + b_co) ^ (b_r & 7)) << 4);
#pragma unroll
            for (int nt = 0; nt < 4; nt++) {
                uint32_t b[2];
                LDSM2(b, Bb + (nt * 8 + b_r) * 128 + bsw);
#pragma unroll
                for (int mt = 0; mt < 4; mt++)
                    MMA16816(c[mt][nt], a[mt], b);
            }
        }
        __syncthreads();
    }

#pragma unroll
    for (int nt = 0; nt < 4; nt++) {
        int col = n0 + wn * 32 + nt * 8 + (lane & 3) * 2;
        float2 bv = *(const float2*)&bias[col];
#pragma unroll
        for (int mt = 0; mt < 4; mt++) {
            int row = m0 + wm * 64 + mt * 16 + (lane >> 2);
            float2 v0 = { c[mt][nt][0] + bv.x, c[mt][nt][1] + bv.y };
            float2 v1 = { c[mt][nt][2] + bv.x, c[mt][nt][3] + bv.y };
            *(float2*)&C[(size_t)row * GG + col] = v0;
            *(float2*)&C[(size_t)(row + 8) * GG + col] = v1;
        }
    }
}

// ---------------- persistent mma.sync GRU layer ----------------
// 128 CTAs: ng = blockIdx.x & 15 (32 h-cols -> 96 gate rows), mg = blockIdx.x >> 4.
// Barrier scope: 16 CTAs sharing mg. xp/hold prefetched into registers before MMA.
__global__ void __launch_bounds__(256, 1) gru_mma(
    const float* __restrict__ xp,
    const __nv_bfloat16* __restrict__ Whi_g, const __nv_bfloat16* __restrict__ Wlo_g,
    const float* __restrict__ bhh,
    __nv_bfloat16* __restrict__ seqhi, __nv_bfloat16* __restrict__ seqlo)
{
    extern __shared__ char smx[];
    const uint32_t sb = smem_u32(smx);
    float* sbias = (float*)smx;                    // 96 floats
    const uint32_t W_HI = 512;
    const uint32_t W_LO = 512 + 98304;
    const uint32_t A_HI = 512 + 196608;
    const uint32_t A_LO = A_HI + 16384;
    float* dred = (float*)(smx + A_HI);            // overlay: [2][16][stride 100]

    const int tid = threadIdx.x, w = tid >> 5, lane = tid & 31;
    const int nq = w & 3, kh = w >> 2;
    const int ng = blockIdx.x & 15, mg = blockIdx.x >> 4;

    // persistent W slice, swizzled
    const __nv_bfloat16* wh = Whi_g + (size_t)ng * 96 * 512;
    const __nv_bfloat16* wl = Wlo_g + (size_t)ng * 96 * 512;
    for (int idx = tid; idx < 6144; idx += 256) {
        int r = idx >> 6, cc = idx & 63;
        uint32_t off = (uint32_t)(r * 1024 + ((cc ^ (r & 7)) << 4));
        *(uint4*)(smx + W_HI + off) = *(const uint4*)(wh + r * 512 + cc * 8);
        *(uint4*)(smx + W_LO + off) = *(const uint4*)(wl + r * 512 + cc * 8);
    }
    if (tid < 96) sbias[tid] = bhh[(tid >> 5) * 512 + ng * 32 + (tid & 31)];

    // zero owned region of initial state
    if (tid < 128) {
        int b = mg * 16 + (tid >> 3);
        int cc = ng * 32 + (tid & 7) * 4;
        float4 z4 = {0.f, 0.f, 0.f, 0.f};
        uint2 zb = {0u, 0u};
        *(float4*)&g_h[0][b * 512 + cc] = z4;
        *(uint2*)&g_hbhi[0][b * 512 + cc] = zb;
        *(uint2*)&g_hblo[0][b * 512 + cc] = zb;
    }

    unsigned gen = g_genv[mg * 32];
    group_barrier(mg, gen);

    const int a_r  = (lane & 7) + ((lane >> 3) & 1) * 8;
    const int a_co = lane >> 4;
    const int b_r  = lane & 7;
    const int b_co = (lane >> 3) & 1;
    const uint32_t AbHi = sb + A_HI + a_r * 1024;
    const uint32_t AbLo = sb + A_LO + a_r * 1024;
    uint32_t BbHi[3], BbLo[3];
#pragma unroll
    for (int f = 0; f < 3; f++) {
        int n = nq * 24 + f * 8 + b_r;
        BbHi[f] = sb + W_HI + n * 1024;
        BbLo[f] = sb + W_LO + n * 1024;
    }

    // epilogue/prefetch thread mapping: (b0, cc0) and (b0+8, cc0)
    const int b0  = tid >> 5;          // 0..7
    const int cc0 = tid & 31;          // 0..31
    const int bg0 = mg * 16 + b0;
    const int bg1 = bg0 + 8;
    const int hc0 = ng * 32 + cc0;
    const float* xpp0 = xp + (size_t)bg0 * TT * GG + hc0;
    const float* xpp1 = xp + (size_t)bg1 * TT * GG + hc0;

    for (int t = 0; t < TT; t++) {
        const int cur = t & 1, nxt = cur ^ 1;

        // stage h tile (16 rows x 512, hi+lo) with cp.async
        const __nv_bfloat16* hh = &g_hbhi[cur][(size_t)mg * 16 * 512];
        const __nv_bfloat16* hl = &g_hblo[cur][(size_t)mg * 16 * 512];
#pragma unroll
        for (int j = 0; j < 4; j++) {
            int idx = tid + j * 256;
            int r = idx >> 6, cc = idx & 63;
            uint32_t off = (uint32_t)(r * 1024 + ((cc ^ (r & 7)) << 4));
            CP16(sb + A_HI + off, hh + r * 512 + cc * 8);
            CP16(sb + A_LO + off, hl + r * 512 + cc * 8);
        }
        CPCOMMIT();

        // prefetch xp + hold for this step (latency hidden under MMA loop)
        const size_t to = (size_t)t * GG;
        float pxr0 = __ldg(xpp0 + to),        pxr1 = __ldg(xpp1 + to);
        float pxz0 = __ldg(xpp0 + to + 512),  pxz1 = __ldg(xpp1 + to + 512);
        float pxn0 = __ldg(xpp0 + to + 1024), pxn1 = __ldg(xpp1 + to + 1024);
        float phold0 = g_h[cur][bg0 * 512 + hc0];
        float phold1 = g_h[cur][bg1 * 512 + hc0];

        CPWAIT0();
        __syncthreads();

        float acc[3][4];
#pragma unroll
        for (int f = 0; f < 3; f++)
#pragma unroll
            for (int q = 0; q < 4; q++) acc[f][q] = 0.f;

#pragma unroll
        for (int kk0 = 0; kk0 < 16; kk0++) {
            int kk = kh * 16 + kk0;
            uint32_t ahi[4], alo[4];
            uint32_t asw = (uint32_t)(((2 * kk + a_co) ^ (a_r & 7)) << 4);
            LDSM4(ahi, AbHi + asw);
            LDSM4(alo, AbLo + asw);
            uint32_t bsw = (uint32_t)(((2 * kk + b_co) ^ (b_r & 7)) << 4);
#pragma unroll
            for (int f = 0; f < 3; f++) {
                uint32_t bh[2], bl[2];
                LDSM2(bh, BbHi[f] + bsw);
                LDSM2(bl, BbLo[f] + bsw);
                MMA16816(acc[f], ahi, bh);
                MMA16816(acc[f], alo, bh);
                MMA16816(acc[f], ahi, bl);
            }
        }
        __syncthreads();   // all LDSM done before dred overlays the A region

#pragma unroll
        for (int f = 0; f < 3; f++) {
            int colc = nq * 24 + f * 8 + (lane & 3) * 2;
            int br = lane >> 2;
            float* p0 = &dred[(kh * 16 + br) * 100 + colc];
            float* p1 = &dred[(kh * 16 + br + 8) * 100 + colc];
            p0[0] = acc[f][0]; p0[1] = acc[f][1];
            p1[0] = acc[f][2]; p1[1] = acc[f][3];
        }
        __syncthreads();

        // fused gate epilogue: 2 (b, col) pairs per thread, prefetched inputs
#pragma unroll
        for (int pp = 0; pp < 2; pp++) {
            int b = b0 + pp * 8;
            float Dr = dred[b * 100 + cc0]      + dred[(16 + b) * 100 + cc0];
            float Dz = dred[b * 100 + 32 + cc0] + dred[(16 + b) * 100 + 32 + cc0];
            float Dn = dred[b * 100 + 64 + cc0] + dred[(16 + b) * 100 + 64 + cc0];
            float xr = pp ? pxr1 : pxr0;
            float xz = pp ? pxz1 : pxz0;
            float xn = pp ? pxn1 : pxn0;
            float hold = pp ? phold1 : phold0;
            int bg = pp ? bg1 : bg0;
            float r = __fdividef(1.f, 1.f + __expf(-(xr + Dr + sbias[cc0])));
            float z = __fdividef(1.f, 1.f + __expf(-(xz + Dz + sbias[32 + cc0])));
            float pre = xn + r * (Dn + sbias[64 + cc0]);
            float e2 = __expf(2.f * pre);
            float n = 1.f - __fdividef(2.f, e2 + 1.f);
            float hv = (1.f - z) * n + z * hold;
            g_h[nxt][bg * 512 + hc0] = hv;
            __nv_bfloat16 hb = __float2bfloat16(hv);
            float lo = hv - __bfloat162float(hb);
            g_hbhi[nxt][bg * 512 + hc0] = hb;
            g_hblo[nxt][bg * 512 + hc0] = __float2bfloat16(lo);
            if (seqhi) {
                size_t so = ((size_t)bg * TT + t) * HH + hc0;
                seqhi[so] = hb;
                seqlo[so] = __float2bfloat16(lo);
            }
        }
        group_barrier(mg, gen);
    }
}

// ---------------- final linear ----------------
__global__ void final_linear(const float* __restrict__ Wl, const float* __restrict__ bl,
                             float* __restrict__ out)
{
    __shared__ float ssum[4];
    int b = blockIdx.x, tid = threadIdx.x;
    const float* h = &g_h[0][0] + b * 512;     // t=1023 writes buffer 0
    float s = 0.f;
    for (int k = tid; k < 512; k += 128) s += h[k] * Wl[k];
#pragma unroll
    for (int o = 16; o > 0; o >>= 1) s += __shfl_down_sync(0xffffffffu, s, o);
    if ((tid & 31) == 0) ssum[tid >> 5] = s;
    __syncthreads();
    if (tid == 0) out[b] = ssum[0] + ssum[1] + ssum[2] + ssum[3] + bl[0];
}

// ---------------- launch ----------------
extern "C" void kernel_launch(void* const* d_in, const int* in_sizes, int n_in,
                              void* d_out, int out_size)
{
    const float* x    = (const float*)d_in[0];
    const float* Wih0 = (const float*)d_in[1];
    const float* Whh0 = (const float*)d_in[2];
    const float* bih0 = (const float*)d_in[3];
    const float* bhh0 = (const float*)d_in[4];
    const float* Wih1 = (const float*)d_in[5];
    const float* Whh1 = (const float*)d_in[6];
    const float* bih1 = (const float*)d_in[7];
    const float* bhh1 = (const float*)d_in[8];
    const float* Wlin = (const float*)d_in[9];
    const float* blin = (const float*)d_in[10];
    float* out = (float*)d_out;

    float* xp;
    __nv_bfloat16 *xhi, *xlo, *h1hi, *h1lo, *w0hi, *w0lo, *w1hi, *w1lo, *whhhi, *whhlo;
    cudaGetSymbolAddress((void**)&xp, g_xp);
    cudaGetSymbolAddress((void**)&xhi, g_xhi);
    cudaGetSymbolAddress((void**)&xlo, g_xlo);
    cudaGetSymbolAddress((void**)&h1hi, g_h1hi);
    cudaGetSymbolAddress((void**)&h1lo, g_h1lo);
    cudaGetSymbolAddress((void**)&w0hi, g_w0hi);
    cudaGetSymbolAddress((void**)&w0lo, g_w0lo);
    cudaGetSymbolAddress((void**)&w1hi, g_w1hi);
    cudaGetSymbolAddress((void**)&w1lo, g_w1lo);
    cudaGetSymbolAddress((void**)&whhhi, g_whhhi);
    cudaGetSymbolAddress((void**)&whhlo, g_whhlo);
    const size_t WHH_SZ = 16 * 96 * 512;

    const int GEMM_SMEM = 2 * 32768;
    const int GRU_SMEM  = 512 + 2 * 98304 + 2 * 16384;
    cudaFuncSetAttribute(gemm_mma<256>, cudaFuncAttributeMaxDynamicSharedMemorySize, GEMM_SMEM);
    cudaFuncSetAttribute(gemm_mma<512>, cudaFuncAttributeMaxDynamicSharedMemorySize, GEMM_SMEM);
    cudaFuncSetAttribute(gru_mma, cudaFuncAttributeMaxDynamicSharedMemorySize, GRU_SMEM);

    {
        size_t n = (size_t)BB * TT * 256;
        split_f32<<<(unsigned)((n + 255) / 256), 256>>>(x, n, xhi, xlo);
    }
    split_f32<<<(GG * 256 + 255) / 256, 256>>>(Wih0, (size_t)GG * 256, w0hi, w0lo);
    split_f32<<<(GG * 512 + 255) / 256, 256>>>(Wih1, (size_t)GG * 512, w1hi, w1lo);
    split_whh<<<3072, 256>>>(Whh0, whhhi, whhlo);
    split_whh<<<3072, 256>>>(Whh1, whhhi + WHH_SZ, whhlo + WHH_SZ);

    dim3 gg(GG / 128, (BB * TT) / 128);

    gemm_mma<256><<<gg, 256, GEMM_SMEM>>>(xhi, xlo, w0hi, w0lo, bih0, xp);
    gru_mma<<<NCTA, 256, GRU_SMEM>>>(xp, whhhi, whhlo, bhh0, h1hi, h1lo);
    gemm_mma<512><<<gg, 256, GEMM_SMEM>>>(h1hi, h1lo, w1hi, w1lo, bih1, xp);
    gru_mma<<<NCTA, 256, GRU_SMEM>>>(xp, whhhi + WHH_SZ, whhlo + WHH_SZ, bhh1, nullptr, nullptr);
    final_linear<<<BB, 128>>>(Wlin, blin, out);
}

// round 6
// speedup vs baseline: 4.5087x; 1.2718x over previous
#include <cuda_runtime.h>
#include <cuda_bf16.h>
#include <math.h>
#include <stdint.h>

#define BB 128
#define TT 1024
#define HH 512
#define GG 1536
#define NCTA 128

// ---------------- device scratch (no allocation) ----------------
__device__ float g_xp[(size_t)BB * TT * GG];
__device__ __nv_bfloat16 g_xhi[(size_t)BB * TT * 256];
__device__ __nv_bfloat16 g_xlo[(size_t)BB * TT * 256];
__device__ __nv_bfloat16 g_h1hi[(size_t)BB * TT * HH];
__device__ __nv_bfloat16 g_h1lo[(size_t)BB * TT * HH];
__device__ __nv_bfloat16 g_w0hi[GG * 256], g_w0lo[GG * 256];
__device__ __nv_bfloat16 g_w1hi[GG * HH],  g_w1lo[GG * HH];
__device__ __nv_bfloat16 g_whhhi[2][16 * 96 * 512];
__device__ __nv_bfloat16 g_whhlo[2][16 * 96 * 512];
__device__ __nv_bfloat16 g_hbhi[2][BB * HH];
__device__ __nv_bfloat16 g_hblo[2][BB * HH];
// per-CTA progress flags: [mg][ng][pad 128B]; monotonic across launches/replays
__device__ unsigned g_flag[8][16][32];

// ---------------- PTX helpers (baseline PTX only) ----------------
__device__ __forceinline__ uint32_t smem_u32(const void* p) {
    uint32_t a;
    asm("{ .reg .u64 t; cvta.to.shared.u64 t, %1; cvt.u32.u64 %0, t; }" : "=r"(a) : "l"(p));
    return a;
}

#define CP16(dst, src) \
    asm volatile("cp.async.cg.shared.global [%0], [%1], 16;" :: "r"(dst), "l"(src))
#define CPCOMMIT() asm volatile("cp.async.commit_group;")
#define CPWAIT0()  asm volatile("cp.async.wait_group 0;")
#define CPWAIT1()  asm volatile("cp.async.wait_group 1;")

#define LDSM4(r, a) \
    asm volatile("ldmatrix.sync.aligned.m8n8.x4.shared.b16 {%0,%1,%2,%3}, [%4];" \
        : "=r"((r)[0]), "=r"((r)[1]), "=r"((r)[2]), "=r"((r)[3]) : "r"(a))
#define LDSM2(r, a) \
    asm volatile("ldmatrix.sync.aligned.m8n8.x2.shared.b16 {%0,%1}, [%2];" \
        : "=r"((r)[0]), "=r"((r)[1]) : "r"(a))

#define MMA16816(c, a, b) \
    asm volatile("mma.sync.aligned.m16n8k16.row.col.f32.bf16.bf16.f32 " \
        "{%0,%1,%2,%3}, {%4,%5,%6,%7}, {%8,%9}, {%0,%1,%2,%3};" \
        : "+f"((c)[0]), "+f"((c)[1]), "+f"((c)[2]), "+f"((c)[3]) \
        : "r"((a)[0]), "r"((a)[1]), "r"((a)[2]), "r"((a)[3]), "r"((b)[0]), "r"((b)[1]))

__device__ __forceinline__ void relstore(unsigned* p, unsigned v) {
    asm volatile("st.release.gpu.u32 [%0], %1;" :: "l"(p), "r"(v) : "memory");
}
__device__ __forceinline__ unsigned acqload(unsigned* p) {
    unsigned v;
    asm volatile("ld.acquire.gpu.u32 %0, [%1];" : "=r"(v) : "l"(p) : "memory");
    return v;
}

// ---------------- conversions ----------------
__global__ void split_f32(const float* __restrict__ src, size_t n,
                          __nv_bfloat16* __restrict__ hi, __nv_bfloat16* __restrict__ lo) {
    size_t i = (size_t)blockIdx.x * blockDim.x + threadIdx.x;
    if (i < n) {
        float v = src[i];
        __nv_bfloat16 h = __float2bfloat16(v);
        hi[i] = h;
        lo[i] = __float2bfloat16(v - __bfloat162float(h));
    }
}

// reorder Whh [1536,512] -> [16 ng][96][512]
__global__ void split_whh(const float* __restrict__ W,
                          __nv_bfloat16* __restrict__ hi, __nv_bfloat16* __restrict__ lo) {
    int i = blockIdx.x * 256 + threadIdx.x;
    int k = i & 511;
    int ro = i >> 9;
    int ng = ro / 96, j = ro % 96;
    int g = j >> 5, jj = j & 31;
    float v = W[(size_t)(g * 512 + ng * 32 + jj) * 512 + k];
    __nv_bfloat16 h = __float2bfloat16(v);
    hi[i] = h;
    lo[i] = __float2bfloat16(v - __bfloat162float(h));
}

// ---------------- mma.sync GEMM, 3-stage cp.async pipeline ----------------
template <int K>
__global__ void __launch_bounds__(256) gemm_mma(
    const __nv_bfloat16* __restrict__ Ahi, const __nv_bfloat16* __restrict__ Alo,
    const __nv_bfloat16* __restrict__ Bhi, const __nv_bfloat16* __restrict__ Blo,
    const float* __restrict__ bias, float* __restrict__ C)
{
    extern __shared__ char smx[];
    const uint32_t sb = smem_u32(smx);
    const int tid = threadIdx.x, w = tid >> 5, lane = tid & 31;
    const int wm = w >> 2, wn = w & 3;
    const int m0 = blockIdx.y * 128, n0 = blockIdx.x * 128;

    float c[4][4][4];
#pragma unroll
    for (int i = 0; i < 4; i++)
#pragma unroll
        for (int j = 0; j < 4; j++)
#pragma unroll
            for (int q = 0; q < 4; q++) c[i][j][q] = 0.f;

    const int a_r  = (lane & 7) + ((lane >> 3) & 1) * 8;
    const int a_co = lane >> 4;
    const int b_r  = lane & 7;
    const int b_co = (lane >> 3) & 1;

    const int KC = K / 64;
    const int NIT = 3 * KC;

    auto stage = [&](int it, int buf) {
        int p = it / KC;
        int kc = (it - p * KC) * 64;
        const __nv_bfloat16* Ap = (p == 1) ? Alo : Ahi;
        const __nv_bfloat16* Bp = (p == 2) ? Blo : Bhi;
#pragma unroll
        for (int j = 0; j < 4; j++) {
            int idx = tid + j * 256;
            int r = idx >> 3, cc = idx & 7;
            uint32_t off = (uint32_t)(r * 128 + ((cc ^ (r & 7)) << 4));
            CP16(sb + buf * 32768 + off, Ap + (size_t)(m0 + r) * K + kc + cc * 8);
            CP16(sb + buf * 32768 + 16384 + off, Bp + (size_t)(n0 + r) * K + kc + cc * 8);
        }
    };

    stage(0, 0); CPCOMMIT();
    stage(1, 1); CPCOMMIT();
    for (int it = 0; it < NIT; it++) {
        int buf = it % 3;
        CPWAIT1();
        __syncthreads();

        const uint32_t Ab = sb + buf * 32768 + (wm * 64) * 128;
        const uint32_t Bb = sb + buf * 32768 + 16384 + (wn * 32) * 128;
#pragma unroll
        for (int kk = 0; kk < 4; kk++) {
            uint32_t a[4][4];
            uint32_t asw = (uint32_t)(((2 * kk + a_co) ^ (a_r & 7)) << 4);
#pragma unroll
            for (int mt = 0; mt < 4; mt++)
                LDSM4(a[mt], Ab + (mt * 16 + a_r) * 128 + asw);
            uint32_t bsw = (uint32_t)(((2 * kk + b_co) ^ (b_r & 7)) << 4);
#pragma unroll
            for (int nt = 0; nt < 4; nt++) {
                uint32_t b[2];
                LDSM2(b, Bb + (nt * 8 + b_r) * 128 + bsw);
#pragma unroll
                for (int mt = 0; mt < 4; mt++)
                    MMA16816(c[mt][nt], a[mt], b);
            }
        }
        if (it + 2 < NIT) stage(it + 2, (it + 2) % 3);
        CPCOMMIT();
    }

#pragma unroll
    for (int nt = 0; nt < 4; nt++) {
        int col = n0 + wn * 32 + nt * 8 + (lane & 3) * 2;
        float2 bv = *(const float2*)&bias[col];
#pragma unroll
        for (int mt = 0; mt < 4; mt++) {
            int row = m0 + wm * 64 + mt * 16 + (lane >> 2);
            float2 v0 = { c[mt][nt][0] + bv.x, c[mt][nt][1] + bv.y };
            float2 v1 = { c[mt][nt][2] + bv.x, c[mt][nt][3] + bv.y };
            *(float2*)&C[(size_t)row * GG + col] = v0;
            *(float2*)&C[(size_t)(row + 8) * GG + col] = v1;
        }
    }
}

// ---------------- persistent mma.sync GRU layer ----------------
// Flag-based sync: CTA (mg,ng) owns g_flag[mg][ng]. Flag = base + 1 + steps_done.
// Consumers acquire-poll all 16 flags of their mg group before reading h.
__global__ void __launch_bounds__(256, 1) gru_mma(
    const float* __restrict__ xp,
    const __nv_bfloat16* __restrict__ Whi_g, const __nv_bfloat16* __restrict__ Wlo_g,
    const float* __restrict__ bhh,
    __nv_bfloat16* __restrict__ seqhi, __nv_bfloat16* __restrict__ seqlo)
{
    extern __shared__ char smx[];
    const uint32_t sb = smem_u32(smx);
    float* sbias = (float*)smx;                    // 96 floats
    const uint32_t W_HI = 512;
    const uint32_t W_LO = 512 + 98304;
    const uint32_t A_HI = 512 + 196608;
    const uint32_t A_LO = A_HI + 16384;
    float* dred = (float*)(smx + A_HI);            // overlay: [2][16][stride 100]

    const int tid = threadIdx.x, w = tid >> 5, lane = tid & 31;
    const int nq = w & 3, kh = w >> 2;
    const int ng = blockIdx.x & 15, mg = blockIdx.x >> 4;

    const unsigned base = g_flag[mg][ng][0];       // stable between launches

    // persistent W slice, swizzled
    const __nv_bfloat16* wh = Whi_g + (size_t)ng * 96 * 512;
    const __nv_bfloat16* wl = Wlo_g + (size_t)ng * 96 * 512;
    for (int idx = tid; idx < 6144; idx += 256) {
        int r = idx >> 6, cc = idx & 63;
        uint32_t off = (uint32_t)(r * 1024 + ((cc ^ (r & 7)) << 4));
        *(uint4*)(smx + W_HI + off) = *(const uint4*)(wh + r * 512 + cc * 8);
        *(uint4*)(smx + W_LO + off) = *(const uint4*)(wl + r * 512 + cc * 8);
    }
    if (tid < 96) sbias[tid] = bhh[(tid >> 5) * 512 + ng * 32 + (tid & 31)];

    // zero owned region of initial state
    if (tid < 128) {
        int b = mg * 16 + (tid >> 3);
        int cc = ng * 32 + (tid & 7) * 4;
        uint2 zb = {0u, 0u};
        *(uint2*)&g_hbhi[0][b * 512 + cc] = zb;
        *(uint2*)&g_hblo[0][b * 512 + cc] = zb;
    }
    __syncthreads();

    const int a_r  = (lane & 7) + ((lane >> 3) & 1) * 8;
    const int a_co = lane >> 4;
    const int b_r  = lane & 7;
    const int b_co = (lane >> 3) & 1;
    const uint32_t AbHi = sb + A_HI + a_r * 1024;
    const uint32_t AbLo = sb + A_LO + a_r * 1024;
    uint32_t BbHi[3], BbLo[3];
#pragma unroll
    for (int f = 0; f < 3; f++) {
        int n = nq * 24 + f * 8 + b_r;
        BbHi[f] = sb + W_HI + n * 1024;
        BbLo[f] = sb + W_LO + n * 1024;
    }

    // hoist W-hi fragments into registers (loop-invariant over all 1024 steps)
    uint32_t bhr[3][16][2];
#pragma unroll
    for (int kk0 = 0; kk0 < 16; kk0++) {
        int kk = kh * 16 + kk0;
        uint32_t bsw = (uint32_t)(((2 * kk + b_co) ^ (b_r & 7)) << 4);
#pragma unroll
        for (int f = 0; f < 3; f++)
            LDSM2(bhr[f][kk0], BbHi[f] + bsw);
    }

    // init-done flag (release: makes zero-init visible to group)
    if (tid == 0) relstore(&g_flag[mg][ng][0], base + 1);

    // epilogue/prefetch thread mapping
    const int b0  = tid >> 5;
    const int cc0 = tid & 31;
    const int bg0 = mg * 16 + b0;
    const int bg1 = bg0 + 8;
    const int hc0 = ng * 32 + cc0;
    const float* xpp0 = xp + (size_t)bg0 * TT * GG + hc0;
    const float* xpp1 = xp + (size_t)bg1 * TT * GG + hc0;

    for (int t = 0; t < TT; t++) {
        const int cur = t & 1, nxt = cur ^ 1;

        // prefetch xp + own hold (no inter-CTA dependency) before the flag wait
        const size_t to = (size_t)t * GG;
        float pxr0 = __ldg(xpp0 + to),        pxr1 = __ldg(xpp1 + to);
        float pxz0 = __ldg(xpp0 + to + 512),  pxz1 = __ldg(xpp1 + to + 512);
        float pxn0 = __ldg(xpp0 + to + 1024), pxn1 = __ldg(xpp1 + to + 1024);
        float phold0 = __bfloat162float(g_hbhi[cur][bg0 * 512 + hc0])
                     + __bfloat162float(g_hblo[cur][bg0 * 512 + hc0]);
        float phold1 = __bfloat162float(g_hbhi[cur][bg1 * 512 + hc0])
                     + __bfloat162float(g_hblo[cur][bg1 * 512 + hc0]);

        // wait for all producers of h[cur]
        if (tid < 16) {
            const unsigned tgt = base + 1 + (unsigned)t;
            while ((int)(acqload(&g_flag[mg][tid][0]) - tgt) < 0) { }
        }
        __syncthreads();

        // stage h tile (16 rows x 512, hi+lo)
        const __nv_bfloat16* hh = &g_hbhi[cur][(size_t)mg * 16 * 512];
        const __nv_bfloat16* hl = &g_hblo[cur][(size_t)mg * 16 * 512];
#pragma unroll
        for (int j = 0; j < 4; j++) {
            int idx = tid + j * 256;
            int r = idx >> 6, cc = idx & 63;
            uint32_t off = (uint32_t)(r * 1024 + ((cc ^ (r & 7)) << 4));
            CP16(sb + A_HI + off, hh + r * 512 + cc * 8);
            CP16(sb + A_LO + off, hl + r * 512 + cc * 8);
        }
        CPCOMMIT(); CPWAIT0();
        __syncthreads();

        float acc[3][4];
#pragma unroll
        for (int f = 0; f < 3; f++)
#pragma unroll
            for (int q = 0; q < 4; q++) acc[f][q] = 0.f;

#pragma unroll
        for (int kk0 = 0; kk0 < 16; kk0++) {
            int kk = kh * 16 + kk0;
            uint32_t ahi[4], alo[4];
            uint32_t asw = (uint32_t)(((2 * kk + a_co) ^ (a_r & 7)) << 4);
            LDSM4(ahi, AbHi + asw);
            LDSM4(alo, AbLo + asw);
            uint32_t bsw = (uint32_t)(((2 * kk + b_co) ^ (b_r & 7)) << 4);
#pragma unroll
            for (int f = 0; f < 3; f++) {
                uint32_t bl[2];
                LDSM2(bl, BbLo[f] + bsw);
                MMA16816(acc[f], ahi, bhr[f][kk0]);
                MMA16816(acc[f], alo, bhr[f][kk0]);
                MMA16816(acc[f], ahi, bl);
            }
        }
        __syncthreads();   // all LDSM done before dred overlays the A region

#pragma unroll
        for (int f = 0; f < 3; f++) {
            int colc = nq * 24 + f * 8 + (lane & 3) * 2;
            int br = lane >> 2;
            float* p0 = &dred[(kh * 16 + br) * 100 + colc];
            float* p1 = &dred[(kh * 16 + br + 8) * 100 + colc];
            p0[0] = acc[f][0]; p0[1] = acc[f][1];
            p1[0] = acc[f][2]; p1[1] = acc[f][3];
        }
        __syncthreads();

        // fused gate epilogue
#pragma unroll
        for (int pp = 0; pp < 2; pp++) {
            int b = b0 + pp * 8;
            float Dr = dred[b * 100 + cc0]      + dred[(16 + b) * 100 + cc0];
            float Dz = dred[b * 100 + 32 + cc0] + dred[(16 + b) * 100 + 32 + cc0];
            float Dn = dred[b * 100 + 64 + cc0] + dred[(16 + b) * 100 + 64 + cc0];
            float xr = pp ? pxr1 : pxr0;
            float xz = pp ? pxz1 : pxz0;
            float xn = pp ? pxn1 : pxn0;
            float hold = pp ? phold1 : phold0;
            int bg = pp ? bg1 : bg0;
            float r = __fdividef(1.f, 1.f + __expf(-(xr + Dr + sbias[cc0])));
            float z = __fdividef(1.f, 1.f + __expf(-(xz + Dz + sbias[32 + cc0])));
            float pre = xn + r * (Dn + sbias[64 + cc0]);
            float e2 = __expf(2.f * pre);
            float n = 1.f - __fdividef(2.f, e2 + 1.f);
            float hv = (1.f - z) * n + z * hold;
            __nv_bfloat16 hb = __float2bfloat16(hv);
            float lo = hv - __bfloat162float(hb);
            __nv_bfloat16 lb = __float2bfloat16(lo);
            g_hbhi[nxt][bg * 512 + hc0] = hb;
            g_hblo[nxt][bg * 512 + hc0] = lb;
            if (seqhi) {
                size_t so = ((size_t)bg * TT + t) * HH + hc0;
                seqhi[so] = hb;
                seqlo[so] = lb;
            }
        }
        __syncthreads();    // all h writes done before release
        if (tid == 0) relstore(&g_flag[mg][ng][0], base + 2 + (unsigned)t);
    }
}

// ---------------- final linear ----------------
__global__ void final_linear(const float* __restrict__ Wl, const float* __restrict__ bl,
                             float* __restrict__ out)
{
    __shared__ float ssum[4];
    int b = blockIdx.x, tid = threadIdx.x;
    float s = 0.f;
    for (int k = tid; k < 512; k += 128) {
        float hv = __bfloat162float(g_hbhi[0][b * 512 + k])
                 + __bfloat162float(g_hblo[0][b * 512 + k]);
        s += hv * Wl[k];
    }
#pragma unroll
    for (int o = 16; o > 0; o >>= 1) s += __shfl_down_sync(0xffffffffu, s, o);
    if ((tid & 31) == 0) ssum[tid >> 5] = s;
    __syncthreads();
    if (tid == 0) out[b] = ssum[0] + ssum[1] + ssum[2] + ssum[3] + bl[0];
}

// ---------------- launch ----------------
extern "C" void kernel_launch(void* const* d_in, const int* in_sizes, int n_in,
                              void* d_out, int out_size)
{
    const float* x    = (const float*)d_in[0];
    const float* Wih0 = (const float*)d_in[1];
    const float* Whh0 = (const float*)d_in[2];
    const float* bih0 = (const float*)d_in[3];
    const float* bhh0 = (const float*)d_in[4];
    const float* Wih1 = (const float*)d_in[5];
    const float* Whh1 = (const float*)d_in[6];
    const float* bih1 = (const float*)d_in[7];
    const float* bhh1 = (const float*)d_in[8];
    const float* Wlin = (const float*)d_in[9];
    const float* blin = (const float*)d_in[10];
    float* out = (float*)d_out;

    float* xp;
    __nv_bfloat16 *xhi, *xlo, *h1hi, *h1lo, *w0hi, *w0lo, *w1hi, *w1lo, *whhhi, *whhlo;
    cudaGetSymbolAddress((void**)&xp, g_xp);
    cudaGetSymbolAddress((void**)&xhi, g_xhi);
    cudaGetSymbolAddress((void**)&xlo, g_xlo);
    cudaGetSymbolAddress((void**)&h1hi, g_h1hi);
    cudaGetSymbolAddress((void**)&h1lo, g_h1lo);
    cudaGetSymbolAddress((void**)&w0hi, g_w0hi);
    cudaGetSymbolAddress((void**)&w0lo, g_w0lo);
    cudaGetSymbolAddress((void**)&w1hi, g_w1hi);
    cudaGetSymbolAddress((void**)&w1lo, g_w1lo);
    cudaGetSymbolAddress((void**)&whhhi, g_whhhi);
    cudaGetSymbolAddress((void**)&whhlo, g_whhlo);
    const size_t WHH_SZ = 16 * 96 * 512;

    const int GEMM_SMEM = 3 * 32768;
    const int GRU_SMEM  = 512 + 2 * 98304 + 2 * 16384;
    cudaFuncSetAttribute(gemm_mma<256>, cudaFuncAttributeMaxDynamicSharedMemorySize, GEMM_SMEM);
    cudaFuncSetAttribute(gemm_mma<512>, cudaFuncAttributeMaxDynamicSharedMemorySize, GEMM_SMEM);
    cudaFuncSetAttribute(gru_mma, cudaFuncAttributeMaxDynamicSharedMemorySize, GRU_SMEM);

    {
        size_t n = (size_t)BB * TT * 256;
        split_f32<<<(unsigned)((n + 255) / 256), 256>>>(x, n, xhi, xlo);
    }
    split_f32<<<(GG * 256 + 255) / 256, 256>>>(Wih0, (size_t)GG * 256, w0hi, w0lo);
    split_f32<<<(GG * 512 + 255) / 256, 256>>>(Wih1, (size_t)GG * 512, w1hi, w1lo);
    split_whh<<<3072, 256>>>(Whh0, whhhi, whhlo);
    split_whh<<<3072, 256>>>(Whh1, whhhi + WHH_SZ, whhlo + WHH_SZ);

    dim3 gg(GG / 128, (BB * TT) / 128);

    gemm_mma<256><<<gg, 256, GEMM_SMEM>>>(xhi, xlo, w0hi, w0lo, bih0, xp);
    gru_mma<<<NCTA, 256, GRU_SMEM>>>(xp, whhhi, whhlo, bhh0, h1hi, h1lo);
    gemm_mma<512><<<gg, 256, GEMM_SMEM>>>(h1hi, h1lo, w1hi, w1lo, bih1, xp);
    gru_mma<<<NCTA, 256, GRU_SMEM>>>(xp, whhhi + WHH_SZ, whhlo + WHH_SZ, bhh1, nullptr, nullptr);
    final_linear<<<BB, 128>>>(Wlin, blin, out);
}